// round 1
// baseline (speedup 1.0000x reference)
#include <cuda_runtime.h>
#include <stdint.h>

#define N_STRUCT   1000
#define ATOMS      100
#define N_SAMP     100000
#define N_GRAD     500000
#define DFEAT      128

// gradient row = 3*128 floats = 384 floats = 96 float4
#define ROW_F4     96
#define GRAD_OUT_OFFSET (N_STRUCT * DFEAT)          // 128000 floats
#define GRAD_OUT_F4     ((N_GRAD * 0) + (100000LL * 384 / 4))  // 9,600,000 float4

// ---------------------------------------------------------------------------
// Zero the gradient-output region (poisoned to 0xAA by harness).
// ---------------------------------------------------------------------------
__global__ void zero_grad_kernel(float4* __restrict__ out4, long long n4) {
    long long i = (long long)blockIdx.x * blockDim.x + threadIdx.x;
    if (i < n4) out4[i] = make_float4(0.f, 0.f, 0.f, 0.f);
}

// ---------------------------------------------------------------------------
// Per-structure sum of value rows. structure_ids is SORTED, so each block
// binary-searches its [lo,hi) row range; 128 threads = 128 feature lanes.
// Coalesced 512B reads per row, single coalesced write. No atomics.
// ---------------------------------------------------------------------------
__global__ void values_kernel(const float* __restrict__ values,
                              const int*   __restrict__ sid,
                              float*       __restrict__ out) {
    int s = blockIdx.x;
    int d = threadIdx.x;

    __shared__ int s_lo, s_hi;
    if (threadIdx.x == 0) {
        int lo = 0, hi = N_SAMP;
        while (lo < hi) { int m = (lo + hi) >> 1; if (sid[m] < s) lo = m + 1; else hi = m; }
        s_lo = lo;
        lo = s_lo; hi = N_SAMP;
        while (lo < hi) { int m = (lo + hi) >> 1; if (sid[m] < s + 1) lo = m + 1; else hi = m; }
        s_hi = lo;
    }
    __syncthreads();

    float acc = 0.f;
    for (int r = s_lo; r < s_hi; ++r)
        acc += values[(long long)r * DFEAT + d];
    out[(long long)s * DFEAT + d] = acc;
}

// ---------------------------------------------------------------------------
// Gradient scatter-add. One warp per gradient row (1536 B). Each lane streams
// 3 float4 (.cs: read-once) and issues red.global.add.v4.f32 into the dense
// (structure*ATOMS + atom) output row. Vector RED = 4x fewer LSU issues.
// ---------------------------------------------------------------------------
__global__ void grad_kernel(const float4* __restrict__ grad4,
                            const int*    __restrict__ gstruct,
                            const int*    __restrict__ gatom,
                            float*        __restrict__ out_grad) {
    long long gtid = (long long)blockIdx.x * blockDim.x + threadIdx.x;
    long long row  = gtid >> 5;
    int lane = threadIdx.x & 31;
    if (row >= N_GRAD) return;

    int seg = gstruct[row] * ATOMS + gatom[row];
    const float4* src = grad4 + row * ROW_F4;
    float* dst = out_grad + (long long)seg * (3 * DFEAT);

    #pragma unroll
    for (int k = 0; k < 3; ++k) {
        float4 v = __ldcs(src + lane + k * 32);
        float* p = dst + (long long)(lane + k * 32) * 4;
        asm volatile("red.global.add.v4.f32 [%0], {%1,%2,%3,%4};"
                     :: "l"(p), "f"(v.x), "f"(v.y), "f"(v.z), "f"(v.w)
                     : "memory");
    }
}

// ---------------------------------------------------------------------------
extern "C" void kernel_launch(void* const* d_in, const int* in_sizes, int n_in,
                              void* d_out, int out_size) {
    const float*  values     = (const float*)d_in[0];
    const int*    sid        = (const int*)  d_in[1];
    const float4* grad4      = (const float4*)d_in[2];
    const int*    gstruct    = (const int*)  d_in[3];
    const int*    gatom      = (const int*)  d_in[4];

    float* out      = (float*)d_out;
    float* out_grad = out + GRAD_OUT_OFFSET;

    // 1) zero gradient-output region (100000 * 384 floats = 9.6M float4)
    const long long n4 = 100000LL * 384 / 4;
    {
        int threads = 256;
        long long blocks = (n4 + threads - 1) / threads;
        zero_grad_kernel<<<(unsigned)blocks, threads>>>((float4*)out_grad, n4);
    }

    // 2) per-structure value sums (independent of step 1)
    values_kernel<<<N_STRUCT, DFEAT>>>(values, sid, out);

    // 3) gradient scatter-add (after zeroing, same stream => ordered)
    {
        int threads = 256;                       // 8 warps/block
        long long warps = N_GRAD;
        long long blocks = (warps * 32 + threads - 1) / threads;
        grad_kernel<<<(unsigned)blocks, threads>>>(grad4, gstruct, gatom, out_grad);
    }
}